// round 10
// baseline (speedup 1.0000x reference)
#include <cuda_runtime.h>
#include <cuda_bf16.h>
#include <cstdint>

#define KC    512
#define DD    64
#define NN    2048
#define BB    64
#define TM    128
#define NTILES 1024          // (BB*NN)/TM
#define NTHREADS 512
#define GRID  148
#define L2E   1.4426950408889634f

// barrier ids: full0=1 full1=2 empty0=3 empty1=4 consumer-red=5
#define BAR_SYNC(id, cnt)   asm volatile("bar.sync %0, %1;"   :: "r"(id), "r"(cnt) : "memory")
#define BAR_ARRIVE(id, cnt) asm volatile("bar.arrive %0, %1;" :: "r"(id), "r"(cnt) : "memory")

// ---------------- smem layout (dynamic) ----------------
#define SMEM_AH   0          // 16KB  A hi (single buffer)
#define SMEM_BH   16384      // 64KB
#define SMEM_BL   81920      // 64KB  (BL = BH + 65536)
#define SMEM_CW   147456     // float2[512] 4KB
#define SMEM_BUF  151552     // 2 stages x 32KB fragment ring
#define SMEM_F2S  217088     // float[128]
#define SMEM_RED  217600     // float[8] + int flag
#define SMEM_TOTAL 217664

__device__ float g_part[NTILES];
__device__ int   g_count;    // zero-init; self-resets each launch

// ---------------- helpers ----------------
__device__ __forceinline__ uint32_t smem_u32(const void* p) {
    uint32_t a;
    asm("{ .reg .u64 t; cvta.to.shared.u64 t, %1; cvt.u32.u64 %0, t; }" : "=r"(a) : "l"(p));
    return a;
}
__device__ __forceinline__ float ex2f(float x) {
    float r; asm("ex2.approx.ftz.f32 %0, %1;" : "=f"(r) : "f"(x)); return r;
}
#define SWZ128(off) ((off) ^ (((off) >> 3) & 0x70))

__device__ __forceinline__ void ldsm4(uint32_t addr, uint32_t* r) {
    asm volatile("ldmatrix.sync.aligned.m8n8.x4.shared.b16 {%0,%1,%2,%3}, [%4];"
        : "=r"(r[0]), "=r"(r[1]), "=r"(r[2]), "=r"(r[3]) : "r"(addr));
}
__device__ __forceinline__ void mma_bf16(float* c, const uint32_t* a, const uint32_t* b) {
    asm volatile(
        "mma.sync.aligned.m16n8k16.row.col.f32.bf16.bf16.f32 "
        "{%0,%1,%2,%3}, {%4,%5,%6,%7}, {%8,%9}, {%0,%1,%2,%3};"
        : "+f"(c[0]), "+f"(c[1]), "+f"(c[2]), "+f"(c[3])
        : "r"(a[0]), "r"(a[1]), "r"(a[2]), "r"(a[3]), "r"(b[0]), "r"(b[1]));
}
__device__ __forceinline__ void sts128(uint32_t addr, const float* v) {
    asm volatile("st.shared.v4.b32 [%0], {%1,%2,%3,%4};"
        :: "r"(addr), "f"(v[0]), "f"(v[1]), "f"(v[2]), "f"(v[3]) : "memory");
}
__device__ __forceinline__ void lds128(uint32_t addr, float* v) {
    asm volatile("ld.shared.v4.b32 {%0,%1,%2,%3}, [%4];"
        : "=f"(v[0]), "=f"(v[1]), "=f"(v[2]), "=f"(v[3]) : "r"(addr));
}

// split 8 floats -> (hi bf16, lo bf16) packed pairwise; ss += sum of squares
__device__ __forceinline__ void split8(const float* v, uint4& hi, uint4& lo, float& ss) {
    float r[8]; __nv_bfloat16 h[8];
#pragma unroll
    for (int i = 0; i < 8; i++) {
        float a = v[i];
        ss = fmaf(a, a, ss);
        h[i] = __float2bfloat16(a);
        r[i] = a - __bfloat162float(h[i]);
    }
    uint32_t* hp = (uint32_t*)&hi;
    uint32_t* lp = (uint32_t*)&lo;
#pragma unroll
    for (int i = 0; i < 4; i++) {
        __nv_bfloat162 th = __nv_bfloat162(h[2*i], h[2*i+1]);
        __nv_bfloat162 tl = __floats2bfloat162_rn(r[2*i], r[2*i+1]);
        hp[i] = *(uint32_t*)&th;
        lp[i] = *(uint32_t*)&tl;
    }
}
// round 8 floats -> hi bf16 packed; ss += sum of squares (fp32 exact)
__device__ __forceinline__ void round8(const float* v, uint4& hi, float& ss) {
    __nv_bfloat16 h[8];
#pragma unroll
    for (int i = 0; i < 8; i++) {
        float a = v[i];
        ss = fmaf(a, a, ss);
        h[i] = __float2bfloat16(a);
    }
    uint32_t* hp = (uint32_t*)&hi;
#pragma unroll
    for (int i = 0; i < 4; i++) {
        __nv_bfloat162 th = __nv_bfloat162(h[2*i], h[2*i+1]);
        hp[i] = *(uint32_t*)&th;
    }
}

// 32-col chunk, 2-term (ah x bh + ah x bl), term-major (8 indep HMMAs per wave)
__device__ __forceinline__ void mma_chunk32(
    float acc[2][4][4], const uint32_t ahc[2][4][4],
    uint32_t blx, uint32_t bcol_base) {
#pragma unroll
    for (int mt = 0; mt < 2; mt++)
#pragma unroll
        for (int nt = 0; nt < 4; nt++)
#pragma unroll
            for (int q = 0; q < 4; q++) acc[mt][nt][q] = 0.f;

#pragma unroll
    for (int kt = 0; kt < 4; kt++) {
        const uint32_t kb = ((uint32_t)(kt * 32)) ^ blx;
        uint32_t bh[2][4], bl[2][4];
#pragma unroll
        for (int np = 0; np < 2; np++) {
            const uint32_t bb = bcol_base + (uint32_t)(np * 16) * 128 + kb;
            ldsm4(bb,         bh[np]);
            ldsm4(bb + 65536, bl[np]);
        }
#pragma unroll
        for (int mt = 0; mt < 2; mt++)
#pragma unroll
            for (int np = 0; np < 2; np++)
#pragma unroll
                for (int h = 0; h < 2; h++)
                    mma_bf16(acc[mt][np*2+h], ahc[mt][kt], &bh[np][h*2]);
#pragma unroll
        for (int mt = 0; mt < 2; mt++)
#pragma unroll
            for (int np = 0; np < 2; np++)
#pragma unroll
                for (int h = 0; h < 2; h++)
                    mma_bf16(acc[mt][np*2+h], ahc[mt][kt], &bl[np][h*2]);
    }
}

// ---------------------------------------------------------------------------
__global__ void __launch_bounds__(NTHREADS, 1)
main_kernel(const float* __restrict__ F,
            const float* __restrict__ C,
            const float* __restrict__ psi,
            const float* __restrict__ betap,
            float* __restrict__ out) {
    extern __shared__ __align__(1024) char smem[];
    const uint32_t sb = smem_u32(smem);
    const int tid  = threadIdx.x;
    const int lane = tid & 31;
    const int wid  = tid >> 5;          // 0..15

    float*  red = (float*)(smem + SMEM_RED);
    int*    flg = (int*)(smem + SMEM_RED + 32);
    float2* cw  = (float2*)(smem + SMEM_CW);
    float*  f2s = (float*)(smem + SMEM_F2S);

    const float beta = *betap;
    const float l2nb = -beta * L2E;          // < 0
    const float coef = -2.0f * l2nb;         // > 0

    // ---- softmax(psi): scratch in BUF region ----
    {
        float* rtmp = (float*)(smem + SMEM_BUF);
        float* ews  = rtmp + 512;
        float p = psi[tid];
        rtmp[tid] = p;
        __syncthreads();
#pragma unroll
        for (int s = 256; s > 0; s >>= 1) {
            if (tid < s) rtmp[tid] = fmaxf(rtmp[tid], rtmp[tid + s]);
            __syncthreads();
        }
        float mx = rtmp[0];
        __syncthreads();
        float e = ex2f((p - mx) * L2E);
        ews[tid] = e;
        rtmp[tid] = e;
        __syncthreads();
#pragma unroll
        for (int s = 256; s > 0; s >>= 1) {
            if (tid < s) rtmp[tid] += rtmp[tid + s];
            __syncthreads();
        }
        float rden = 1.0f / rtmp[0];
        __syncthreads();

        // ---- convert centers -> Bh/Bl (SW128); c2 partials also in BUF ----
        float* c2p = (float*)(smem + SMEM_BUF) + 1024;   // 4096 floats
#pragma unroll
        for (int k = 0; k < 8; k++) {
            int i = tid + k * NTHREADS;
            int r = i >> 3, ck = i & 7;
            float v[8];
            const float4* src = (const float4*)(C + (size_t)r * DD + ck * 8);
            *(float4*)&v[0] = src[0];
            *(float4*)&v[4] = src[1];
            uint4 hi, lo; float ss = 0.f;
            split8(v, hi, lo, ss);
            c2p[i] = ss;
            uint32_t sw = SWZ128((uint32_t)(r * 128 + ck * 16));
            *(uint4*)(smem + SMEM_BH + sw) = hi;
            *(uint4*)(smem + SMEM_BL + sw) = lo;
        }
        __syncthreads();
        {
            float s = 0.f;
#pragma unroll
            for (int k = 0; k < 8; k++) s += c2p[tid * 8 + k];
            cw[tid] = make_float2(l2nb * s, ews[tid] * rden);
        }
        __syncthreads();   // BUF free after this
    }

    // ---- role setup ----
    const bool producer = (wid < 8);
    const int p   = producer ? wid : (wid - 8);   // matched pair index 0..7
    const int rb  = (p & 3) * 32;                 // 32-row block
    const int cb0 = (p >> 2) * 256;               // 256-col half
    // producer ldmatrix lane addressing
    const int arow = lane & 15;
    const uint32_t alx = (uint32_t)(((lane >> 4) * 16) ^ ((arow & 7) * 16));
    const uint32_t abase = sb + SMEM_AH + (uint32_t)(rb + arow) * 128;
    const int bg = lane >> 3, br = lane & 7;
    const uint32_t blx = (uint32_t)(((bg & 1) * 16) ^ (br * 16));
    const int bnoff = br + (bg >> 1) * 8;
    // fragment ring addressing (both roles)
    const uint32_t ringbase = sb + SMEM_BUF + (uint32_t)p * 4096 + (uint32_t)lane * 128;

    // ================= tile loop (persistent) =================
#pragma unroll 1
    for (int t = blockIdx.x; t < NTILES; t += GRID) {
        // ---- conversion phase (all 512 threads): F tile -> A hi + f2s ----
        {
            const float4* src = (const float4*)(F + (size_t)t * TM * DD);
            const int u0 = tid * 2;          // units of 8 floats; 2 per thread, same row
            const int r  = u0 >> 3;
            float ss = 0.f;
#pragma unroll
            for (int j = 0; j < 2; j++) {
                const int u = u0 + j, ck = u & 7;
                float v[8];
                *(float4*)&v[0] = src[u * 2];
                *(float4*)&v[4] = src[u * 2 + 1];
                uint4 hi;
                round8(v, hi, ss);
                uint32_t sw = SWZ128((uint32_t)(r * 128 + ck * 16));
                *(uint4*)(smem + SMEM_AH + sw) = hi;
            }
            ss += __shfl_xor_sync(0xFFFFFFFFu, ss, 1);
            ss += __shfl_xor_sync(0xFFFFFFFFu, ss, 2);
            if ((tid & 3) == 0) f2s[r] = l2nb * ss;
        }
        __syncthreads();   // B1: A + f2s visible

        if (producer) {
            // cache A-hi fragments for all 4 k-steps
            uint32_t ahc[2][4][4];
#pragma unroll
            for (int kt = 0; kt < 4; kt++) {
                const uint32_t ka = ((uint32_t)(kt * 32)) ^ alx;
                ldsm4(abase + ka,        ahc[0][kt]);
                ldsm4(abase + 2048 + ka, ahc[1][kt]);
            }
            float acc[2][4][4];
#pragma unroll 1
            for (int c = 0; c < 8; c++) {
                const int s = c & 1;
                if (c >= 2) BAR_SYNC(3 + s, NTHREADS);       // wait empty
                const int cb = cb0 + c * 32;
                mma_chunk32(acc, ahc, blx,
                            sb + SMEM_BH + (uint32_t)(cb + bnoff) * 128);
                const uint32_t bb = ringbase + (uint32_t)s * 32768;
#pragma unroll
                for (int mt = 0; mt < 2; mt++)
#pragma unroll
                    for (int nt = 0; nt < 4; nt++) {
                        const int w = mt * 4 + nt;
                        sts128(bb + (uint32_t)((w ^ (lane & 7)) << 4), acc[mt][nt]);
                    }
                BAR_ARRIVE(1 + s, NTHREADS);                 // signal full
            }
        } else {
            // per-tile row constants
            const int rr = rb + (lane >> 2);
            const float f2a = f2s[rr],      f2b = f2s[rr + 8];
            const float f2c = f2s[rr + 16], f2d = f2s[rr + 24];
            float score = 0.f;
#pragma unroll 1
            for (int c = 0; c < 8; c++) {
                const int s = c & 1;
                BAR_SYNC(1 + s, NTHREADS);                   // wait full
                const uint32_t bb = ringbase + (uint32_t)s * 32768;
                float v[32];
#pragma unroll
                for (int w = 0; w < 8; w++)
                    lds128(bb + (uint32_t)((w ^ (lane & 7)) << 4), v + w * 4);

                const int ccol = cb0 + c * 32 + 2 * (lane & 3);
#pragma unroll
                for (int w = 0; w < 8; w++) {
                    const int mt = w >> 2, nt = w & 3;
                    const float4 cwv = *(const float4*)(cw + ccol + nt * 8);
                    const float f20 = mt ? f2c : f2a;
                    const float f21 = mt ? f2d : f2b;
                    const float* a = v + w * 4;
                    float g0 = fminf(fmaf(coef, a[0], f20 + cwv.x), 0.f);
                    float g1 = fminf(fmaf(coef, a[1], f20 + cwv.z), 0.f);
                    float g2 = fminf(fmaf(coef, a[2], f21 + cwv.x), 0.f);
                    float g3 = fminf(fmaf(coef, a[3], f21 + cwv.z), 0.f);
                    score = fmaf(cwv.y, ex2f(g0), score);
                    score = fmaf(cwv.w, ex2f(g1), score);
                    score = fmaf(cwv.y, ex2f(g2), score);
                    score = fmaf(cwv.w, ex2f(g3), score);
                }
                if (c < 6) BAR_ARRIVE(3 + s, NTHREADS);      // signal empty
            }
            // consumer-side reduction -> g_part[t]
#pragma unroll
            for (int o = 16; o > 0; o >>= 1)
                score += __shfl_xor_sync(0xFFFFFFFFu, score, o);
            if (lane == 0) red[p] = score;
            BAR_SYNC(5, 256);
            if (wid == 8 && lane == 0) {
                float ssum = 0.f;
#pragma unroll
                for (int w = 0; w < 8; w++) ssum += red[w];
                g_part[t] = ssum;
            }
        }
        __syncthreads();   // B2: tile end — ring + A reusable
    }

    // ---- last CTA folds partials into out ----
    __threadfence();
    if (tid == 0) {
        int pc = atomicAdd(&g_count, 1);
        *flg = (pc == GRID - 1);
    }
    __syncthreads();
    if (*flg) {
        __threadfence();
        if (tid < BB) {
            float s = 0.f;
#pragma unroll
            for (int i = 0; i < NTILES / BB; i++) s += g_part[tid * (NTILES / BB) + i];
            out[tid] = s * (1.0f / NN);
        }
        if (tid == 0) g_count = 0;   // reset for next graph replay
    }
}

// ---------------------------------------------------------------------------
extern "C" void kernel_launch(void* const* d_in, const int* in_sizes, int n_in,
                              void* d_out, int out_size) {
    const float* F       = (const float*)d_in[0];
    const float* centers = (const float*)d_in[1];
    const float* psi     = (const float*)d_in[2];
    const float* beta    = (const float*)d_in[3];
    float* out           = (float*)d_out;

    cudaFuncSetAttribute(main_kernel, cudaFuncAttributeMaxDynamicSharedMemorySize, SMEM_TOTAL);
    main_kernel<<<GRID, NTHREADS, SMEM_TOTAL>>>(F, centers, psi, beta, out);
}

// round 11
// speedup vs baseline: 1.6496x; 1.6496x over previous
#include <cuda_runtime.h>
#include <cuda_fp16.h>
#include <cuda_bf16.h>
#include <cstdint>

#define KC    512
#define DD    64
#define NN    2048
#define BB    64
#define TM    128
#define NTILES 1024          // (BB*NN)/TM
#define NTHREADS 256
#define GRID  148
#define L2E   1.4426950408889634f

// ---------------- smem layout (dynamic) ----------------
#define SMEM_A0   0          // 16KB (A fp16, buf 0)
#define SMEM_A1   16384      // 16KB (A fp16, buf 1)
#define SMEM_BH   32768      // 512 x 128B fp16 (64KB)
#define SMEM_CW   98304      // float2[512] 4KB
#define SMEM_F2P0 102400     // float[1024] 4KB
#define SMEM_F2P1 106496     // 4KB
#define SMEM_F2S0 110592     // float[128]
#define SMEM_F2S1 111104     // float[128]
#define SMEM_RED  111616     // float[8] + int flag
#define SMEM_TOTAL 111680

__device__ float g_part[NTILES];
__device__ int   g_count;    // zero-init; self-resets each launch

// ---------------- helpers ----------------
__device__ __forceinline__ uint32_t smem_u32(const void* p) {
    uint32_t a;
    asm("{ .reg .u64 t; cvta.to.shared.u64 t, %1; cvt.u32.u64 %0, t; }" : "=r"(a) : "l"(p));
    return a;
}
__device__ __forceinline__ float ex2f(float x) {
    float r; asm("ex2.approx.ftz.f32 %0, %1;" : "=f"(r) : "f"(x)); return r;
}
#define SWZ128(off) ((off) ^ (((off) >> 3) & 0x70))

__device__ __forceinline__ void ldsm4(uint32_t addr, uint32_t* r) {
    asm volatile("ldmatrix.sync.aligned.m8n8.x4.shared.b16 {%0,%1,%2,%3}, [%4];"
        : "=r"(r[0]), "=r"(r[1]), "=r"(r[2]), "=r"(r[3]) : "r"(addr));
}
__device__ __forceinline__ void mma_f16(float* c, const uint32_t* a, const uint32_t* b) {
    asm volatile(
        "mma.sync.aligned.m16n8k16.row.col.f32.f16.f16.f32 "
        "{%0,%1,%2,%3}, {%4,%5,%6,%7}, {%8,%9}, {%0,%1,%2,%3};"
        : "+f"(c[0]), "+f"(c[1]), "+f"(c[2]), "+f"(c[3])
        : "r"(a[0]), "r"(a[1]), "r"(a[2]), "r"(a[3]), "r"(b[0]), "r"(b[1]));
}

// round 8 floats -> fp16 packed pairwise; ss += sum of squares (fp32 exact)
__device__ __forceinline__ void hround8(const float* v, uint4& hi, float& ss) {
    uint32_t* hp = (uint32_t*)&hi;
#pragma unroll
    for (int i = 0; i < 4; i++) {
        float a0 = v[2*i], a1 = v[2*i+1];
        ss = fmaf(a0, a0, ss);
        ss = fmaf(a1, a1, ss);
        __half2 th = __floats2half2_rn(a0, a1);
        hp[i] = *(uint32_t*)&th;
    }
}

// 32-col chunk MMA, single-term fp16, A fragments cached.
__device__ __forceinline__ void mma_chunk32(
    float acc[2][4][4], const uint32_t ahc[2][4][4],
    uint32_t blx, uint32_t bcol_base) {
#pragma unroll
    for (int mt = 0; mt < 2; mt++)
#pragma unroll
        for (int nt = 0; nt < 4; nt++)
#pragma unroll
            for (int q = 0; q < 4; q++) acc[mt][nt][q] = 0.f;

#pragma unroll
    for (int kt = 0; kt < 4; kt++) {
        const uint32_t kb = ((uint32_t)(kt * 32)) ^ blx;
        uint32_t bh[2][4];
#pragma unroll
        for (int np = 0; np < 2; np++)
            ldsm4(bcol_base + (uint32_t)(np * 16) * 128 + kb, bh[np]);
        // 8 independent HMMAs per k-step
#pragma unroll
        for (int mt = 0; mt < 2; mt++)
#pragma unroll
            for (int np = 0; np < 2; np++)
#pragma unroll
                for (int h = 0; h < 2; h++)
                    mma_f16(acc[mt][np*2+h], ahc[mt][kt], &bh[np][h*2]);
    }
}

__device__ __forceinline__ void epi_chunk32(
    const float acc[2][4][4], const float* __restrict__ f2s,
    const float2* __restrict__ cw, int cb, int rb, int lane,
    float coef, float& score) {
    const int ccol = cb + 2 * (lane & 3);
#pragma unroll
    for (int mt = 0; mt < 2; mt++) {
        const int r0 = rb + mt * 16 + (lane >> 2);
        const float f20 = f2s[r0], f21 = f2s[r0 + 8];
#pragma unroll
        for (int nt = 0; nt < 4; nt++) {
            const float4 cwv = *(const float4*)(cw + ccol + nt * 8);
            const float* a = acc[mt][nt];
            float g0 = fminf(fmaf(coef, a[0], f20 + cwv.x), 0.f);
            float g1 = fminf(fmaf(coef, a[1], f20 + cwv.z), 0.f);
            float g2 = fminf(fmaf(coef, a[2], f21 + cwv.x), 0.f);
            float g3 = fminf(fmaf(coef, a[3], f21 + cwv.z), 0.f);
            score = fmaf(cwv.y, ex2f(g0), score);
            score = fmaf(cwv.w, ex2f(g1), score);
            score = fmaf(cwv.y, ex2f(g2), score);
            score = fmaf(cwv.w, ex2f(g3), score);
        }
    }
}

// ---------------------------------------------------------------------------
__global__ void __launch_bounds__(NTHREADS, 1)
main_kernel(const float* __restrict__ F,
            const float* __restrict__ C,
            const float* __restrict__ psi,
            const float* __restrict__ betap,
            float* __restrict__ out) {
    extern __shared__ __align__(1024) char smem[];
    const uint32_t sb = smem_u32(smem);
    const int tid  = threadIdx.x;
    const int lane = tid & 31;
    const int wid  = tid >> 5;

    float*  red = (float*)(smem + SMEM_RED);
    int*    flg = (int*)(smem + SMEM_RED + 32);
    float2* cw  = (float2*)(smem + SMEM_CW);

    const float beta = *betap;
    const float l2nb = -beta * L2E;          // < 0
    const float coef = -2.0f * l2nb;         // > 0

    // ---- softmax(psi) (f2p0 region as scratch) ----
    {
        float* rtmp = (float*)(smem + SMEM_F2P0);
        float* ews  = rtmp + 256;            // [256..767]
        float p0 = psi[tid], p1 = psi[tid + 256];
        rtmp[tid] = fmaxf(p0, p1);
        __syncthreads();
#pragma unroll
        for (int s = 128; s > 0; s >>= 1) {
            if (tid < s) rtmp[tid] = fmaxf(rtmp[tid], rtmp[tid + s]);
            __syncthreads();
        }
        float mx = rtmp[0];
        __syncthreads();
        float e0 = ex2f((p0 - mx) * L2E), e1 = ex2f((p1 - mx) * L2E);
        ews[tid] = e0; ews[tid + 256] = e1;
        rtmp[tid] = e0 + e1;
        __syncthreads();
#pragma unroll
        for (int s = 128; s > 0; s >>= 1) {
            if (tid < s) rtmp[tid] += rtmp[tid + s];
            __syncthreads();
        }
        float rden = 1.0f / rtmp[0];
        __syncthreads();

        // ---- convert centers -> B fp16 (SW128), c2 partials in A region ----
        float* c2p = (float*)(smem + SMEM_A0);    // 4096 floats scratch (A0+A1)
        for (int i = tid; i < KC * 8; i += NTHREADS) {
            int r = i >> 3, ck = i & 7;
            float v[8];
            const float4* src = (const float4*)(C + (size_t)r * DD + ck * 8);
            *(float4*)&v[0] = src[0];
            *(float4*)&v[4] = src[1];
            uint4 hi; float ss = 0.f;
            hround8(v, hi, ss);
            c2p[i] = ss;
            uint32_t sw = SWZ128((uint32_t)(r * 128 + ck * 16));
            *(uint4*)(smem + SMEM_BH + sw) = hi;
        }
        __syncthreads();
        for (int j = tid; j < KC; j += NTHREADS) {
            float s = 0.f;
#pragma unroll
            for (int k = 0; k < 8; k++) s += c2p[j * 8 + k];
            cw[j] = make_float2(l2nb * s, ews[j] * rden);
        }
        __syncthreads();   // scratch (A0/A1, f2p0) free after this
    }

    // ---- per-warp ldmatrix lane addressing ----
    const int rb  = (wid & 3) * 32;          // 32-row block
    const int cb0 = (wid >> 2) * 256;        // 256-col half
    const int ncrot = (wid & 1) * 4;         // anti-phase over 8 chunks
    const int arow = lane & 15;
    const uint32_t alx = (uint32_t)(((lane >> 4) * 16) ^ ((arow & 7) * 16));
    const uint32_t arowoff = (uint32_t)(rb + arow) * 128;
    const int bg = lane >> 3, br = lane & 7;
    const uint32_t blx = (uint32_t)(((bg & 1) * 16) ^ (br * 16));
    const int bnoff = br + (bg >> 1) * 8;

    // ---- prologue: convert first tile into buffer 0 ----
    {
        const float4* src = (const float4*)(F + (size_t)blockIdx.x * TM * DD);
        float* f2pn = (float*)(smem + SMEM_F2P0);
#pragma unroll
        for (int k = 0; k < 4; k++) {
            int i = tid + k * NTHREADS;
            int r = i >> 3, ck = i & 7;
            float v[8];
            *(float4*)&v[0] = src[2*i];
            *(float4*)&v[4] = src[2*i+1];
            uint4 hi; float ss = 0.f;
            hround8(v, hi, ss);
            f2pn[i] = ss;
            uint32_t sw = SWZ128((uint32_t)(r * 128 + ck * 16));
            *(uint4*)(smem + SMEM_A0 + sw) = hi;
        }
    }

    int pcur = 0;

    // ================= tile loop (persistent) =================
#pragma unroll 1
    for (int t = blockIdx.x; t < NTILES; t += GRID, pcur ^= 1) {
        __syncthreads();   // B1: A(cur)/f2p(cur) conversion visible

        float* f2pc = (float*)(smem + (pcur ? SMEM_F2P1 : SMEM_F2P0));
        float* f2sc = (float*)(smem + (pcur ? SMEM_F2S1 : SMEM_F2S0));
        const uint32_t abase = sb + (pcur ? SMEM_A1 : SMEM_A0) + arowoff;

        if (tid < TM) {
            float s = 0.f;
#pragma unroll
            for (int k = 0; k < 8; k++) s += f2pc[tid * 8 + k];
            f2sc[tid] = l2nb * s;
        }
        __syncthreads();   // B2: f2s visible

        // cache A fragments for all 4 k-steps (32 regs)
        uint32_t ahc[2][4][4];
#pragma unroll
        for (int kt = 0; kt < 4; kt++) {
            const uint32_t ka = ((uint32_t)(kt * 32)) ^ alx;
            ldsm4(abase + ka,        ahc[0][kt]);
            ldsm4(abase + 2048 + ka, ahc[1][kt]);
        }

        float score = 0.f;
        float accA[2][4][4], accB[2][4][4];

        // chunk 0 MMA
        {
            const int cb = cb0 + (ncrot & 7) * 32;
            mma_chunk32(accA, ahc, blx,
                        sb + SMEM_BH + (uint32_t)(cb + bnoff) * 128);
        }

        // prefetch+convert next tile (overlaps tensor work)
        if (t + GRID < NTILES) {
            const float4* src = (const float4*)(F + (size_t)(t + GRID) * TM * DD);
            float* f2pn = (float*)(smem + (pcur ? SMEM_F2P0 : SMEM_F2P1));
            const uint32_t an = (pcur ? SMEM_A0 : SMEM_A1);
#pragma unroll
            for (int k = 0; k < 4; k++) {
                int i = tid + k * NTHREADS;
                int r = i >> 3, ck = i & 7;
                float v[8];
                *(float4*)&v[0] = src[2*i];
                *(float4*)&v[4] = src[2*i+1];
                uint4 hi; float ss = 0.f;
                hround8(v, hi, ss);
                f2pn[i] = ss;
                uint32_t sw = SWZ128((uint32_t)(r * 128 + ck * 16));
                *(uint4*)(smem + an + sw) = hi;
            }
        }

        // pipelined chunks 1..7: MMA(c) then epilogue(c-1)
#pragma unroll
        for (int c = 1; c < 8; c++) {
            const int cb  = cb0 + ((c + ncrot) & 7) * 32;
            const int cbp = cb0 + ((c - 1 + ncrot) & 7) * 32;
            if (c & 1) {
                mma_chunk32(accB, ahc, blx,
                            sb + SMEM_BH + (uint32_t)(cb + bnoff) * 128);
                epi_chunk32(accA, f2sc, cw, cbp, rb, lane, coef, score);
            } else {
                mma_chunk32(accA, ahc, blx,
                            sb + SMEM_BH + (uint32_t)(cb + bnoff) * 128);
                epi_chunk32(accB, f2sc, cw, cbp, rb, lane, coef, score);
            }
        }
        epi_chunk32(accB, f2sc, cw, cb0 + ((7 + ncrot) & 7) * 32, rb, lane, coef, score);

        // ---- shuffle reduction ----
#pragma unroll
        for (int o = 16; o > 0; o >>= 1)
            score += __shfl_xor_sync(0xFFFFFFFFu, score, o);
        if (lane == 0) red[wid] = score;
        __syncthreads();   // B3: red ready; all reads of cur buffers done
        if (tid == 0) {
            float s = 0.f;
#pragma unroll
            for (int w = 0; w < 8; w++) s += red[w];
            g_part[t] = s;
        }
    }

    // ---- last CTA folds partials into out ----
    __threadfence();
    if (tid == 0) {
        int p = atomicAdd(&g_count, 1);
        *flg = (p == GRID - 1);
    }
    __syncthreads();
    if (*flg) {
        __threadfence();
        if (tid < BB) {
            float s = 0.f;
#pragma unroll
            for (int i = 0; i < NTILES / BB; i++) s += g_part[tid * (NTILES / BB) + i];
            out[tid] = s * (1.0f / NN);
        }
        if (tid == 0) g_count = 0;   // reset for next graph replay
    }
}

// ---------------------------------------------------------------------------
extern "C" void kernel_launch(void* const* d_in, const int* in_sizes, int n_in,
                              void* d_out, int out_size) {
    const float* F       = (const float*)d_in[0];
    const float* centers = (const float*)d_in[1];
    const float* psi     = (const float*)d_in[2];
    const float* beta    = (const float*)d_in[3];
    float* out           = (float*)d_out;

    cudaFuncSetAttribute(main_kernel, cudaFuncAttributeMaxDynamicSharedMemorySize, SMEM_TOTAL);
    main_kernel<<<GRID, NTHREADS, SMEM_TOTAL>>>(F, centers, psi, beta, out);
}

// round 12
// speedup vs baseline: 1.9191x; 1.1634x over previous
#include <cuda_runtime.h>
#include <cuda_fp16.h>
#include <cstdint>

#define KC    512
#define DD    64
#define NN    2048
#define BB    64
#define TM    128
#define NTILES 1024          // (BB*NN)/TM
#define NTHREADS 256
#define GRID  148
#define L2E   1.4426950408889634f

// ---------------- smem layout (dynamic) ----------------
#define SMEM_A0   0          // 16KB (A fp16, buf 0)
#define SMEM_A1   16384      // 16KB (A fp16, buf 1)
#define SMEM_BH   32768      // 512 x 128B fp16 (64KB), pre-scaled by coef
#define SMEM_QW   98304      // float[512] q_j = w*Ec*2^16  (2KB)
#define SMEM_F2P0 100352     // float[1024] 4KB
#define SMEM_F2P1 104448     // 4KB
#define SMEM_EF0  108544     // float[128]  Ef*2^-16
#define SMEM_EF1  109056     // float[128]
#define SMEM_RED  109568     // float[8] + int flag
#define SMEM_TOTAL 109632

__device__ float g_part[NTILES];
__device__ int   g_count;    // zero-init; self-resets each launch

// ---------------- helpers ----------------
__device__ __forceinline__ uint32_t smem_u32(const void* p) {
    uint32_t a;
    asm("{ .reg .u64 t; cvta.to.shared.u64 t, %1; cvt.u32.u64 %0, t; }" : "=r"(a) : "l"(p));
    return a;
}
__device__ __forceinline__ float ex2f(float x) {
    float r; asm("ex2.approx.ftz.f32 %0, %1;" : "=f"(r) : "f"(x)); return r;
}
#define SWZ128(off) ((off) ^ (((off) >> 3) & 0x70))

__device__ __forceinline__ void ldsm4(uint32_t addr, uint32_t* r) {
    asm volatile("ldmatrix.sync.aligned.m8n8.x4.shared.b16 {%0,%1,%2,%3}, [%4];"
        : "=r"(r[0]), "=r"(r[1]), "=r"(r[2]), "=r"(r[3]) : "r"(addr));
}
__device__ __forceinline__ void mma_f16(float* c, const uint32_t* a, const uint32_t* b) {
    asm volatile(
        "mma.sync.aligned.m16n8k16.row.col.f32.f16.f16.f32 "
        "{%0,%1,%2,%3}, {%4,%5,%6,%7}, {%8,%9}, {%0,%1,%2,%3};"
        : "+f"(c[0]), "+f"(c[1]), "+f"(c[2]), "+f"(c[3])
        : "r"(a[0]), "r"(a[1]), "r"(a[2]), "r"(a[3]), "r"(b[0]), "r"(b[1]));
}

// round 8 floats (scaled) -> fp16 packed pairwise; ss += sum of squares (unscaled)
__device__ __forceinline__ void hround8(const float* v, float scale, uint4& hi, float& ss) {
    uint32_t* hp = (uint32_t*)&hi;
#pragma unroll
    for (int i = 0; i < 4; i++) {
        float a0 = v[2*i], a1 = v[2*i+1];
        ss = fmaf(a0, a0, ss);
        ss = fmaf(a1, a1, ss);
        __half2 th = __floats2half2_rn(a0 * scale, a1 * scale);
        hp[i] = *(uint32_t*)&th;
    }
}

// 32-col chunk MMA, single-term fp16, A fragments cached.
__device__ __forceinline__ void mma_chunk32(
    float acc[2][4][4], const uint32_t ahc[2][4][4],
    uint32_t blx, uint32_t bcol_base) {
#pragma unroll
    for (int mt = 0; mt < 2; mt++)
#pragma unroll
        for (int nt = 0; nt < 4; nt++)
#pragma unroll
            for (int q = 0; q < 4; q++) acc[mt][nt][q] = 0.f;

#pragma unroll
    for (int kt = 0; kt < 4; kt++) {
        const uint32_t kb = ((uint32_t)(kt * 32)) ^ blx;
        uint32_t bh[2][4];
#pragma unroll
        for (int np = 0; np < 2; np++)
            ldsm4(bcol_base + (uint32_t)(np * 16) * 128 + kb, bh[np]);
#pragma unroll
        for (int mt = 0; mt < 2; mt++)
#pragma unroll
            for (int np = 0; np < 2; np++)
#pragma unroll
                for (int h = 0; h < 2; h++)
                    mma_f16(acc[mt][np*2+h], ahc[mt][kt], &bh[np][h*2]);
    }
}

// epilogue: s[slot] += q_j * 2^acc  (acc is already coef*f.c)
__device__ __forceinline__ void epi_chunk32(
    const float acc[2][4][4], const float* __restrict__ qw,
    int cb, int lane, float* s) {
    const int ccol = cb + 2 * (lane & 3);
#pragma unroll
    for (int mt = 0; mt < 2; mt++) {
#pragma unroll
        for (int nt = 0; nt < 4; nt++) {
            const float2 qv = *(const float2*)(qw + ccol + nt * 8);
            const float* a = acc[mt][nt];
            s[mt*2+0] = fmaf(qv.x, ex2f(a[0]), s[mt*2+0]);
            s[mt*2+0] = fmaf(qv.y, ex2f(a[1]), s[mt*2+0]);
            s[mt*2+1] = fmaf(qv.x, ex2f(a[2]), s[mt*2+1]);
            s[mt*2+1] = fmaf(qv.y, ex2f(a[3]), s[mt*2+1]);
        }
    }
}

// ---------------------------------------------------------------------------
__global__ void __launch_bounds__(NTHREADS, 1)
main_kernel(const float* __restrict__ F,
            const float* __restrict__ C,
            const float* __restrict__ psi,
            const float* __restrict__ betap,
            float* __restrict__ out) {
    extern __shared__ __align__(1024) char smem[];
    const uint32_t sb = smem_u32(smem);
    const int tid  = threadIdx.x;
    const int lane = tid & 31;
    const int wid  = tid >> 5;

    float* red = (float*)(smem + SMEM_RED);
    int*   flg = (int*)(smem + SMEM_RED + 32);
    float* qw  = (float*)(smem + SMEM_QW);

    const float beta = *betap;
    const float l2nb = -beta * L2E;          // < 0
    const float coef = -2.0f * l2nb;         // = 2*beta*log2e > 0

    // ---- softmax(psi) (f2p0 region as scratch) ----
    {
        float* rtmp = (float*)(smem + SMEM_F2P0);
        float* ews  = rtmp + 256;            // [256..767]
        float p0 = psi[tid], p1 = psi[tid + 256];
        rtmp[tid] = fmaxf(p0, p1);
        __syncthreads();
#pragma unroll
        for (int s = 128; s > 0; s >>= 1) {
            if (tid < s) rtmp[tid] = fmaxf(rtmp[tid], rtmp[tid + s]);
            __syncthreads();
        }
        float mx = rtmp[0];
        __syncthreads();
        float e0 = ex2f((p0 - mx) * L2E), e1 = ex2f((p1 - mx) * L2E);
        ews[tid] = e0; ews[tid + 256] = e1;
        rtmp[tid] = e0 + e1;
        __syncthreads();
#pragma unroll
        for (int s = 128; s > 0; s >>= 1) {
            if (tid < s) rtmp[tid] += rtmp[tid + s];
            __syncthreads();
        }
        float rden = 1.0f / rtmp[0];
        __syncthreads();

        // ---- convert centers -> B fp16 scaled by coef (SW128); c2 partials ----
        float* c2p = (float*)(smem + SMEM_A0);    // 4096 floats scratch (A0+A1)
        for (int i = tid; i < KC * 8; i += NTHREADS) {
            int r = i >> 3, ck = i & 7;
            float v[8];
            const float4* src = (const float4*)(C + (size_t)r * DD + ck * 8);
            *(float4*)&v[0] = src[0];
            *(float4*)&v[4] = src[1];
            uint4 hi; float ss = 0.f;
            hround8(v, coef, hi, ss);
            c2p[i] = ss;
            uint32_t sw = SWZ128((uint32_t)(r * 128 + ck * 16));
            *(uint4*)(smem + SMEM_BH + sw) = hi;
        }
        __syncthreads();
        for (int j = tid; j < KC; j += NTHREADS) {
            float s = 0.f;
#pragma unroll
            for (int k = 0; k < 8; k++) s += c2p[j * 8 + k];
            // q_j = w_j * 2^(l2nb*c2 + 16)
            qw[j] = ews[j] * rden * ex2f(fmaf(l2nb, s, 16.0f));
        }
        __syncthreads();   // scratch (A0/A1, f2p0) free after this
    }

    // ---- per-warp ldmatrix lane addressing ----
    const int rb  = (wid & 3) * 32;          // 32-row block
    const int cb0 = (wid >> 2) * 256;        // 256-col half
    const int ncrot = (wid & 1) * 4;         // anti-phase over 8 chunks
    const int arow = lane & 15;
    const uint32_t alx = (uint32_t)(((lane >> 4) * 16) ^ ((arow & 7) * 16));
    const uint32_t arowoff = (uint32_t)(rb + arow) * 128;
    const int bg = lane >> 3, br = lane & 7;
    const uint32_t blx = (uint32_t)(((bg & 1) * 16) ^ (br * 16));
    const int bnoff = br + (bg >> 1) * 8;
    const int rr = rb + (lane >> 2);         // epilogue row slot base

    // ---- prologue: convert first tile into buffer 0 ----
    {
        const float4* src = (const float4*)(F + (size_t)blockIdx.x * TM * DD);
        float* f2pn = (float*)(smem + SMEM_F2P0);
#pragma unroll
        for (int k = 0; k < 4; k++) {
            int i = tid + k * NTHREADS;
            int r = i >> 3, ck = i & 7;
            float v[8];
            *(float4*)&v[0] = src[2*i];
            *(float4*)&v[4] = src[2*i+1];
            uint4 hi; float ss = 0.f;
            hround8(v, 1.0f, hi, ss);
            f2pn[i] = ss;
            uint32_t sw = SWZ128((uint32_t)(r * 128 + ck * 16));
            *(uint4*)(smem + SMEM_A0 + sw) = hi;
        }
    }

    int pcur = 0;

    // ================= tile loop (persistent) =================
#pragma unroll 1
    for (int t = blockIdx.x; t < NTILES; t += GRID, pcur ^= 1) {
        __syncthreads();   // B1: A(cur)/f2p(cur) conversion visible

        float* f2pc = (float*)(smem + (pcur ? SMEM_F2P1 : SMEM_F2P0));
        float* efc  = (float*)(smem + (pcur ? SMEM_EF1 : SMEM_EF0));
        const uint32_t abase = sb + (pcur ? SMEM_A1 : SMEM_A0) + arowoff;

        if (tid < TM) {
            float s = 0.f;
#pragma unroll
            for (int k = 0; k < 8; k++) s += f2pc[tid * 8 + k];
            // Ef = 2^(l2nb*f2 - 16)
            efc[tid] = ex2f(fmaf(l2nb, s, -16.0f));
        }
        __syncthreads();   // B2: Ef visible

        // cache A fragments for all 4 k-steps (32 regs)
        uint32_t ahc[2][4][4];
#pragma unroll
        for (int kt = 0; kt < 4; kt++) {
            const uint32_t ka = ((uint32_t)(kt * 32)) ^ alx;
            ldsm4(abase + ka,        ahc[0][kt]);
            ldsm4(abase + 2048 + ka, ahc[1][kt]);
        }

        float s4[4] = {0.f, 0.f, 0.f, 0.f};
        float accA[2][4][4], accB[2][4][4];

        // chunk 0 MMA
        {
            const int cb = cb0 + (ncrot & 7) * 32;
            mma_chunk32(accA, ahc, blx,
                        sb + SMEM_BH + (uint32_t)(cb + bnoff) * 128);
        }

        // prefetch+convert next tile (overlaps tensor work)
        if (t + GRID < NTILES) {
            const float4* src = (const float4*)(F + (size_t)(t + GRID) * TM * DD);
            float* f2pn = (float*)(smem + (pcur ? SMEM_F2P0 : SMEM_F2P1));
            const uint32_t an = (pcur ? SMEM_A0 : SMEM_A1);
#pragma unroll
            for (int k = 0; k < 4; k++) {
                int i = tid + k * NTHREADS;
                int r = i >> 3, ck = i & 7;
                float v[8];
                *(float4*)&v[0] = src[2*i];
                *(float4*)&v[4] = src[2*i+1];
                uint4 hi; float ss = 0.f;
                hround8(v, 1.0f, hi, ss);
                f2pn[i] = ss;
                uint32_t sw = SWZ128((uint32_t)(r * 128 + ck * 16));
                *(uint4*)(smem + an + sw) = hi;
            }
        }

        // pipelined chunks 1..7: MMA(c) then epilogue(c-1)
#pragma unroll
        for (int c = 1; c < 8; c++) {
            const int cb  = cb0 + ((c + ncrot) & 7) * 32;
            const int cbp = cb0 + ((c - 1 + ncrot) & 7) * 32;
            if (c & 1) {
                mma_chunk32(accB, ahc, blx,
                            sb + SMEM_BH + (uint32_t)(cb + bnoff) * 128);
                epi_chunk32(accA, qw, cbp, lane, s4);
            } else {
                mma_chunk32(accA, ahc, blx,
                            sb + SMEM_BH + (uint32_t)(cb + bnoff) * 128);
                epi_chunk32(accB, qw, cbp, lane, s4);
            }
        }
        epi_chunk32(accB, qw, cb0 + ((7 + ncrot) & 7) * 32, lane, s4);

        // fold per-row factors: score = sum_slot Ef[row_slot] * s4[slot]
        float score;
        {
            float4 ef = make_float4(efc[rr], efc[rr + 8], efc[rr + 16], efc[rr + 24]);
            score = s4[0] * ef.x + s4[1] * ef.y + s4[2] * ef.z + s4[3] * ef.w;
        }

        // ---- shuffle reduction ----
#pragma unroll
        for (int o = 16; o > 0; o >>= 1)
            score += __shfl_xor_sync(0xFFFFFFFFu, score, o);
        if (lane == 0) red[wid] = score;
        __syncthreads();   // B3: red ready; all reads of cur buffers done
        if (tid == 0) {
            float s = 0.f;
#pragma unroll
            for (int w = 0; w < 8; w++) s += red[w];
            g_part[t] = s;
        }
    }

    // ---- last CTA folds partials into out ----
    __threadfence();
    if (tid == 0) {
        int p = atomicAdd(&g_count, 1);
        *flg = (p == GRID - 1);
    }
    __syncthreads();
    if (*flg) {
        __threadfence();
        if (tid < BB) {
            float s = 0.f;
#pragma unroll
            for (int i = 0; i < NTILES / BB; i++) s += g_part[tid * (NTILES / BB) + i];
            out[tid] = s * (1.0f / NN);
        }
        if (tid == 0) g_count = 0;   // reset for next graph replay
    }
}

// ---------------------------------------------------------------------------
extern "C" void kernel_launch(void* const* d_in, const int* in_sizes, int n_in,
                              void* d_out, int out_size) {
    const float* F       = (const float*)d_in[0];
    const float* centers = (const float*)d_in[1];
    const float* psi     = (const float*)d_in[2];
    const float* beta    = (const float*)d_in[3];
    float* out           = (float*)d_out;

    cudaFuncSetAttribute(main_kernel, cudaFuncAttributeMaxDynamicSharedMemorySize, SMEM_TOTAL);
    main_kernel<<<GRID, NTHREADS, SMEM_TOTAL>>>(F, centers, psi, beta, out);
}